// round 13
// baseline (speedup 1.0000x reference)
#include <cuda_runtime.h>
#include <cuda_bf16.h>
#include <cuda_fp16.h>
#include <cstdint>

// Problem shape constants (fixed by setup_inputs)
#define MAX_NODES 100000
#define MAX_EDGES 1600000
#define D_IN   256
#define D_HALF 128
#define D_OUT  256   // concat(forward, backward)

#define SCAN_CH 2048        // elems per scan block (512 thr * 4)
#define MAX_SCAN_BLOCKS 64

// ---------------- device scratch (no allocations allowed) ----------------
__device__ int   g_is64;
__device__ int   g_deg_in [MAX_NODES];
__device__ int   g_deg_out[MAX_NODES];
__device__ int   g_off_in [MAX_NODES + 1];
__device__ int   g_off_out[MAX_NODES + 1];
__device__ int   g_fill_in [MAX_NODES];
__device__ int   g_fill_out[MAX_NODES];
__device__ int   g_src_f[MAX_EDGES];
__device__ int   g_src_b[MAX_EDGES];
__device__ float g_rin [MAX_NODES];
__device__ float g_rout[MAX_NODES];
__device__ long long g_bsum[MAX_SCAN_BLOCKS];
__device__ __half g_feat[(size_t)MAX_NODES * D_OUT];      // PRE-SCALED fp16: fwd*rout[n], bwd*rin[n]
__device__ __nv_bfloat16 g_wb [(size_t)256 * 512];        // B [n][512]: 0-255 Whi, 256-511 Wlo

// ---------------- edge accessors (dtype detected at runtime) ----------------
__device__ __forceinline__ int edge_col(const unsigned* __restrict__ w, int e, int is64) {
    return (int)(is64 ? w[2u * (unsigned)e] : w[(unsigned)e]);
}
__device__ __forceinline__ int edge_row(const unsigned* __restrict__ w, int e, int n_edges, int is64) {
    return (int)(is64 ? w[2u * (unsigned)(n_edges + e)] : w[(unsigned)(n_edges + e)]);
}

__global__ void k_detect(const unsigned* __restrict__ w, int n_words_check) {
    __shared__ unsigned s[256];
    unsigned acc = 0;
    for (int i = threadIdx.x; i < n_words_check; i += 256)
        if (i & 1) acc |= w[i];
    s[threadIdx.x] = acc;
    __syncthreads();
    for (int d = 128; d > 0; d >>= 1) {
        if (threadIdx.x < d) s[threadIdx.x] |= s[threadIdx.x + d];
        __syncthreads();
    }
    if (threadIdx.x == 0) g_is64 = (s[0] == 0) ? 1 : 0;
}

__global__ void k_zero(int n_nodes) {
    int i = blockIdx.x * blockDim.x + threadIdx.x;
    if (i < n_nodes) {
        g_deg_in[i]   = 0;
        g_deg_out[i]  = 0;
        g_fill_in[i]  = 0;
        g_fill_out[i] = 0;
    }
}

__global__ void k_hist(const unsigned* __restrict__ w, int n_edges) {
    int e = blockIdx.x * blockDim.x + threadIdx.x;
    if (e < n_edges) {
        int is64 = g_is64;
        atomicAdd(&g_deg_in [edge_col(w, e, is64)], 1);
        atomicAdd(&g_deg_out[edge_row(w, e, n_edges, is64)], 1);
    }
}

// ---------------- multi-block packed exclusive scan ----------------
__global__ __launch_bounds__(512)
void k_scan_part(int n_nodes) {
    __shared__ long long ws[16];
    const int tid = threadIdx.x, lane = tid & 31, wid = tid >> 5;
    int i0 = blockIdx.x * SCAN_CH + tid * 4;
    long long s = 0;
#pragma unroll
    for (int j = 0; j < 4; j++) {
        int i = i0 + j;
        if (i < n_nodes)
            s += ((long long)g_deg_out[i] << 32) | (unsigned)g_deg_in[i];
    }
#pragma unroll
    for (int d = 16; d > 0; d >>= 1) s += __shfl_down_sync(0xffffffff, s, d);
    if (lane == 0) ws[wid] = s;
    __syncthreads();
    if (wid == 0) {
        long long r = (lane < 16) ? ws[lane] : 0;
#pragma unroll
        for (int d = 8; d > 0; d >>= 1) r += __shfl_down_sync(0xffffffff, r, d);
        if (lane == 0) g_bsum[blockIdx.x] = r;
    }
}

__global__ void k_scan_bsum(int nb) {
    int tid = threadIdx.x;                 // 64 threads
    long long v = (tid < nb) ? g_bsum[tid] : 0;
    long long t = v;
#pragma unroll
    for (int d = 1; d < 32; d <<= 1) {
        long long u = __shfl_up_sync(0xffffffff, t, d);
        if ((tid & 31) >= d) t += u;
    }
    __shared__ long long w0tot;
    if (tid == 31) w0tot = t;
    __syncthreads();
    if (tid >= 32) t += w0tot;
    if (tid < nb) g_bsum[tid] = t - v;     // exclusive
}

__global__ __launch_bounds__(512)
void k_scan_final(int n_nodes) {
    __shared__ long long warpsum[16];
    const int tid = threadIdx.x, lane = tid & 31, wid = tid >> 5;
    const long long run = g_bsum[blockIdx.x];
    int i0 = blockIdx.x * SCAN_CH + tid * 4;
    long long v[4];
    long long s = 0;
#pragma unroll
    for (int j = 0; j < 4; j++) {
        int i = i0 + j;
        long long din = 0, dout = 0;
        if (i < n_nodes) {
            din  = g_deg_in[i];
            dout = g_deg_out[i];
            g_rin [i] = rsqrtf((float)(din  + 1));   // +1 self loop
            g_rout[i] = rsqrtf((float)(dout + 1));
        }
        v[j] = (dout << 32) | din;
        s += v[j];
    }
    long long t = s;
#pragma unroll
    for (int d = 1; d < 32; d <<= 1) {
        long long u = __shfl_up_sync(0xffffffff, t, d);
        if (lane >= d) t += u;
    }
    if (lane == 31) warpsum[wid] = t;
    __syncthreads();
    if (wid == 0) {
        long long w = (lane < 16) ? warpsum[lane] : 0;
#pragma unroll
        for (int d = 1; d < 16; d <<= 1) {
            long long u = __shfl_up_sync(0xffffffff, w, d);
            if (lane >= d) w += u;
        }
        if (lane < 16) warpsum[lane] = w;
    }
    __syncthreads();
    long long warpoff = (wid > 0) ? warpsum[wid - 1] : 0;
    long long excl = run + warpoff + (t - s);
#pragma unroll
    for (int j = 0; j < 4; j++) {
        int i = i0 + j;
        if (i < n_nodes) {
            g_off_in [i] = (int)(excl & 0xffffffffLL);
            g_off_out[i] = (int)((unsigned long long)excl >> 32);
        }
        excl += v[j];
        if (i == n_nodes - 1) {
            g_off_in [n_nodes] = (int)(excl & 0xffffffffLL);
            g_off_out[n_nodes] = (int)((unsigned long long)excl >> 32);
        }
    }
}

__global__ void k_fill(const unsigned* __restrict__ w, int n_edges) {
    int e = blockIdx.x * blockDim.x + threadIdx.x;
    if (e >= n_edges) return;
    int is64 = g_is64;
    int c = edge_col(w, e, is64);
    int r = edge_row(w, e, n_edges, is64);
    int p = atomicAdd(&g_fill_in[c], 1);
    g_src_f[g_off_in[c] + p] = r;
    int q = atomicAdd(&g_fill_out[r], 1);
    g_src_b[g_off_out[r] + q] = c;
}

// ---------------- W split prep: g_wb[n][512] = [Whi | Wlo] -------------------
__global__ void k_prep_w(const float* __restrict__ Wf, const float* __restrict__ Wb) {
    int idx = blockIdx.x * blockDim.x + threadIdx.x;
    if (idx >= 256 * 512) return;
    int n = idx >> 9;
    int k = idx & 511;
    int kk = k & 255;
    int sec = k >> 8;
    const float* Wsrc = (n < 128) ? (Wf + (size_t)n * D_IN) : (Wb + (size_t)(n - 128) * D_IN);
    float v = Wsrc[kk];
    __nv_bfloat16 hi = __float2bfloat16(v);
    g_wb[idx] = (sec == 0) ? hi : __float2bfloat16(v - __bfloat162float(hi));
}

// ---------------- mma.sync bf16 GEMM, 128x128 tile @ 512 thr, fused split --------
// Grid: (2, m_tiles) — blockIdx.x = half (0 fwd / 1 bwd), 128 N each.
// 16 warps as 4(M) x 4(N), warp tile 32x32. 8 K-chunks of 32; per chunk
// 3 sections: Ahi*Bhi + Alo*Bhi + Ahi*Blo. Dynamic SMEM 80 KB, occupancy 1.
#define SA_LD 40
#define SMEM_ARR (2 * 128 * SA_LD)     // elems per (hi/lo, A/B) array incl. 2 buffers
#define GEMM_SMEM (4 * SMEM_ARR * 2)   // bytes
__device__ __forceinline__ void mma16816(float* c, const uint32_t* a, const uint32_t* b) {
    asm volatile(
        "mma.sync.aligned.m16n8k16.row.col.f32.bf16.bf16.f32 "
        "{%0,%1,%2,%3}, {%4,%5,%6,%7}, {%8,%9}, {%0,%1,%2,%3};"
        : "+f"(c[0]), "+f"(c[1]), "+f"(c[2]), "+f"(c[3])
        : "r"(a[0]), "r"(a[1]), "r"(a[2]), "r"(a[3]), "r"(b[0]), "r"(b[1]));
}
__device__ __forceinline__ void ldsm4(uint32_t& r0, uint32_t& r1, uint32_t& r2, uint32_t& r3,
                                      uint32_t addr) {
    asm volatile("ldmatrix.sync.aligned.m8n8.x4.shared.b16 {%0,%1,%2,%3}, [%4];"
                 : "=r"(r0), "=r"(r1), "=r"(r2), "=r"(r3) : "r"(addr));
}
// convert 8 contiguous fp32 -> 8 bf16 hi + 8 bf16 lo, store as uint4 pair
__device__ __forceinline__ void cvt_store8(const float4& f0, const float4& f1,
                                           __nv_bfloat16* dh, __nv_bfloat16* dl) {
    float f[8] = {f0.x, f0.y, f0.z, f0.w, f1.x, f1.y, f1.z, f1.w};
    alignas(16) __nv_bfloat16 h[8];
    alignas(16) __nv_bfloat16 l[8];
#pragma unroll
    for (int j = 0; j < 8; j++) {
        h[j] = __float2bfloat16(f[j]);
        l[j] = __float2bfloat16(f[j] - __bfloat162float(h[j]));
    }
    *(uint4*)dh = *(uint4*)h;
    *(uint4*)dl = *(uint4*)l;
}

__global__ __launch_bounds__(512, 1)
void k_gemm_mma(const float* __restrict__ x, int n_nodes) {
    extern __shared__ __nv_bfloat16 smem[];
    __nv_bfloat16* sAh = smem;                 // [2][128*SA_LD]
    __nv_bfloat16* sAl = smem + SMEM_ARR;
    __nv_bfloat16* sBh = smem + 2 * SMEM_ARR;
    __nv_bfloat16* sBl = smem + 3 * SMEM_ARR;

    const int tid  = threadIdx.x;
    const int wid  = tid >> 5;           // 0..15
    const int lane = tid & 31;
    const int qr   = lane >> 2;          // 0..7
    const int qc   = lane & 3;           // 0..3
    const int wm   = (wid & 3) * 32;     // warp M offset in block
    const int wn   = (wid >> 2) * 32;    // warp N offset in block (0..96)
    const int m0   = blockIdx.y * 128;   // M tile
    const int n0   = blockIdx.x * 128;   // N tile = half * 128
    const int half = blockIdx.x;         // 0: fwd (rout scale), 1: bwd (rin scale)

    const int lrow = lane & 15;          // ldmatrix row
    const int lksl = lane >> 4;          // ldmatrix 16B half-select

    // loaders: one A row + one B row per thread, 8 cols at apart*8
    const int arow  = tid >> 2;          // 0..127
    const int apart = tid & 3;
    int anode = m0 + arow; if (anode >= n_nodes) anode = n_nodes - 1;
    const float* ap = x + (size_t)anode * D_IN + apart * 8;
    const __nv_bfloat16* bp = g_wb + (size_t)(n0 + arow) * 512 + apart * 8;
    const int soff = arow * SA_LD + apart * 8;

    float acc[2][4][4];
#pragma unroll
    for (int mt = 0; mt < 2; mt++)
#pragma unroll
        for (int nt = 0; nt < 4; nt++)
#pragma unroll
            for (int q = 0; q < 4; q++) acc[mt][nt][q] = 0.f;

    float4 fa0, fa1;
    uint4 rbh, rbl;

    // preload chunk 0
    fa0 = *(const float4*)(ap);      fa1 = *(const float4*)(ap + 4);
    rbh = *(const uint4*)(bp);
    rbl = *(const uint4*)(bp + 256);
    cvt_store8(fa0, fa1, sAh + soff, sAl + soff);
    *(uint4*)(sBh + soff) = rbh;
    *(uint4*)(sBl + soff) = rbl;
    __syncthreads();

    for (int kc = 0; kc < 8; kc++) {
        const int cur = kc & 1;
        const int nxt = cur ^ 1;
        const int cbo = cur * 128 * SA_LD;
        const int nbo = nxt * 128 * SA_LD;

        if (kc < 7) {
            const int ko = (kc + 1) * 32;
            fa0 = *(const float4*)(ap + ko);     fa1 = *(const float4*)(ap + ko + 4);
            rbh = *(const uint4*)(bp + ko);
            rbl = *(const uint4*)(bp + 256 + ko);
        }

        const uint32_t sah = (uint32_t)__cvta_generic_to_shared(sAh + cbo);
        const uint32_t sal = (uint32_t)__cvta_generic_to_shared(sAl + cbo);
        const uint32_t sbh = (uint32_t)__cvta_generic_to_shared(sBh + cbo);
        const uint32_t sbl = (uint32_t)__cvta_generic_to_shared(sBl + cbo);

#pragma unroll
        for (int ks = 0; ks < 2; ks++) {
            const int kb = ks * 16;
            uint32_t ah[2][4], al[2][4], bh[2][4], bl[2][4];
#pragma unroll
            for (int mt = 0; mt < 2; mt++) {
                uint32_t off = ((wm + mt * 16 + lrow) * SA_LD + kb + lksl * 8) * 2;
                ldsm4(ah[mt][0], ah[mt][1], ah[mt][2], ah[mt][3], sah + off);
                ldsm4(al[mt][0], al[mt][1], al[mt][2], al[mt][3], sal + off);
            }
#pragma unroll
            for (int np = 0; np < 2; np++) {
                uint32_t off = ((wn + np * 16 + lrow) * SA_LD + kb + lksl * 8) * 2;
                ldsm4(bh[np][0], bh[np][1], bh[np][2], bh[np][3], sbh + off);
                ldsm4(bl[np][0], bl[np][1], bl[np][2], bl[np][3], sbl + off);
            }
#pragma unroll
            for (int mt = 0; mt < 2; mt++)
#pragma unroll
                for (int np = 0; np < 2; np++) {
                    uint32_t b0h[2] = { bh[np][0], bh[np][2] };
                    uint32_t b1h[2] = { bh[np][1], bh[np][3] };
                    uint32_t b0l[2] = { bl[np][0], bl[np][2] };
                    uint32_t b1l[2] = { bl[np][1], bl[np][3] };
                    mma16816(acc[mt][np * 2 + 0], ah[mt], b0h);
                    mma16816(acc[mt][np * 2 + 1], ah[mt], b1h);
                    mma16816(acc[mt][np * 2 + 0], al[mt], b0h);
                    mma16816(acc[mt][np * 2 + 1], al[mt], b1h);
                    mma16816(acc[mt][np * 2 + 0], ah[mt], b0l);
                    mma16816(acc[mt][np * 2 + 1], ah[mt], b1l);
                }
        }

        if (kc < 7) {
            cvt_store8(fa0, fa1, sAh + nbo + soff, sAl + nbo + soff);
            *(uint4*)(sBh + nbo + soff) = rbh;
            *(uint4*)(sBl + nbo + soff) = rbl;
            __syncthreads();
        }
    }

    // epilogue: pre-scale by rout (fwd half) / rin (bwd half), write fp16 g_feat
#pragma unroll
    for (int mt = 0; mt < 2; mt++) {
        int r0 = m0 + wm + mt * 16 + qr;
        int r1 = r0 + 8;
        float s0 = 0.f, s1 = 0.f;
        if (r0 < n_nodes) s0 = half ? g_rin[r0] : g_rout[r0];
        if (r1 < n_nodes) s1 = half ? g_rin[r1] : g_rout[r1];
#pragma unroll
        for (int nt = 0; nt < 4; nt++) {
            int cix = n0 + wn + nt * 8 + 2 * qc;
            if (r0 < n_nodes) {
                __half2 v = __floats2half2_rn(s0 * acc[mt][nt][0], s0 * acc[mt][nt][1]);
                *(__half2*)(g_feat + (size_t)r0 * D_OUT + cix) = v;
            }
            if (r1 < n_nodes) {
                __half2 v = __floats2half2_rn(s1 * acc[mt][nt][2], s1 * acc[mt][nt][3]);
                *(__half2*)(g_feat + (size_t)r1 * D_OUT + cix) = v;
            }
        }
    }
}

// ---------------- gather: 1 warp per (node,half); 8B lane loads -------------------
__global__ __launch_bounds__(128)
void k_gather(const float* __restrict__ bias, float* __restrict__ y, int n_nodes) {
    const int w    = threadIdx.x >> 5;       // 0..3
    const int lane = threadIdx.x & 31;
    const int node = blockIdx.x * 2 + (w >> 1);
    const int h    = w & 1;                  // 0: fwd, 1: bwd
    if (node >= n_nodes) return;

    int s, e;
    const int* __restrict__ srcs;
    float rs;
    if (h == 0) {
        s = g_off_in[node]; e = g_off_in[node + 1];
        srcs = g_src_f;
        rs = g_rin[node];
    } else {
        s = g_off_out[node]; e = g_off_out[node + 1];
        srcs = g_src_b;
        rs = g_rout[node];
    }

    const int hp = h * 32 + lane;            // uint2 index in 64-uint2 row
    const uint2* __restrict__ fp = (const uint2*)g_feat;

    float4 acc;
    {
        uint2 v = fp[(size_t)node * 64 + hp];   // self loop (pre-scaled)
        float2 a = __half22float2(*(__half2*)&v.x);
        float2 b = __half22float2(*(__half2*)&v.y);
        acc = make_float4(a.x, a.y, b.x, b.y);
    }
#pragma unroll 4
    for (int k = s; k < e; k++) {
        int src = __ldg(&srcs[k]);
        uint2 v = __ldg(&fp[(size_t)src * 64 + hp]);
        float2 a = __half22float2(*(__half2*)&v.x);
        float2 b = __half22float2(*(__half2*)&v.y);
        acc.x += a.x; acc.y += a.y; acc.z += b.x; acc.w += b.y;
    }

    const int coff = hp * 4;
    float4 b4 = *(const float4*)(bias + coff);
    float4 o = make_float4(b4.x + rs * acc.x, b4.y + rs * acc.y,
                           b4.z + rs * acc.z, b4.w + rs * acc.w);
    *(float4*)(y + (size_t)node * D_OUT + coff) = o;
}

// ---------------- launch ----------------
extern "C" void kernel_launch(void* const* d_in, const int* in_sizes, int n_in,
                              void* d_out, int out_size) {
    const float*    x    = (const float*)d_in[0];
    const unsigned* ew   = (const unsigned*)d_in[1];
    const float*    Wf   = (const float*)d_in[2];
    const float*    Wb   = (const float*)d_in[3];
    const float*    bias = (const float*)d_in[4];
    float* y = (float*)d_out;

    const int n_nodes = in_sizes[0] / D_IN;
    const int n_edges = in_sizes[1] / 2;

    int check = 8192;
    if (check > 2 * n_edges) check = 2 * n_edges;
    k_detect<<<1, 256>>>(ew, check);

    k_zero<<<(n_nodes + 255) / 256, 256>>>(n_nodes);
    k_hist<<<(n_edges + 255) / 256, 256>>>(ew, n_edges);

    const int nb = (n_nodes + SCAN_CH - 1) / SCAN_CH;
    k_scan_part <<<nb, 512>>>(n_nodes);
    k_scan_bsum <<<1, 64>>>(nb);
    k_scan_final<<<nb, 512>>>(n_nodes);

    k_fill<<<(n_edges + 255) / 256, 256>>>(ew, n_edges);

    k_prep_w<<<(256 * 512 + 255) / 256, 256>>>(Wf, Wb);

    cudaFuncSetAttribute(k_gemm_mma, cudaFuncAttributeMaxDynamicSharedMemorySize, GEMM_SMEM);
    dim3 ggrid(2, (n_nodes + 127) / 128);
    k_gemm_mma<<<ggrid, 512, GEMM_SMEM>>>(x, n_nodes);

    dim3 grid_g((n_nodes + 1) / 2, 1);
    k_gather<<<grid_g, 128>>>(bias, y, n_nodes);
}

// round 14
// speedup vs baseline: 1.0179x; 1.0179x over previous
#include <cuda_runtime.h>
#include <cuda_bf16.h>
#include <cuda_fp16.h>
#include <cstdint>

// Problem shape constants (fixed by setup_inputs)
#define MAX_NODES 100000
#define MAX_EDGES 1600000
#define D_IN   256
#define D_HALF 128
#define D_OUT  256   // concat(forward, backward)

#define SCAN_CH 2048        // elems per scan block (512 thr * 4)
#define MAX_SCAN_BLOCKS 64

// ---------------- device scratch (no allocations allowed) ----------------
__device__ int   g_is64;
__device__ int   g_deg_in [MAX_NODES];
__device__ int   g_deg_out[MAX_NODES];
__device__ int   g_off_in [MAX_NODES + 1];
__device__ int   g_off_out[MAX_NODES + 1];
__device__ int   g_fill_in [MAX_NODES];
__device__ int   g_fill_out[MAX_NODES];
__device__ int   g_src_f[MAX_EDGES];
__device__ int   g_src_b[MAX_EDGES];
__device__ float g_rin [MAX_NODES];
__device__ float g_rout[MAX_NODES];
__device__ long long g_bsum[MAX_SCAN_BLOCKS];
__device__ __half g_feat[(size_t)MAX_NODES * D_OUT];      // PRE-SCALED fp16: fwd*rout[n], bwd*rin[n]
__device__ __nv_bfloat16 g_wb [(size_t)256 * 512];        // B [n][512]: 0-255 Whi, 256-511 Wlo

// ---------------- edge accessors (dtype detected at runtime) ----------------
__device__ __forceinline__ int edge_col(const unsigned* __restrict__ w, int e, int is64) {
    return (int)(is64 ? w[2u * (unsigned)e] : w[(unsigned)e]);
}
__device__ __forceinline__ int edge_row(const unsigned* __restrict__ w, int e, int n_edges, int is64) {
    return (int)(is64 ? w[2u * (unsigned)(n_edges + e)] : w[(unsigned)(n_edges + e)]);
}

// ---------------- detect dtype + zero counters (merged) ----------------
__global__ void k_detect_zero(const unsigned* __restrict__ w, int n_words_check, int n_nodes) {
    int i = blockIdx.x * blockDim.x + threadIdx.x;
    if (i < n_nodes) {
        g_deg_in[i]   = 0;
        g_deg_out[i]  = 0;
        g_fill_in[i]  = 0;
        g_fill_out[i] = 0;
    }
    if (blockIdx.x == 0) {
        __shared__ unsigned s[256];
        unsigned acc = 0;
        for (int k = threadIdx.x; k < n_words_check; k += 256)
            if (k & 1) acc |= w[k];
        s[threadIdx.x] = acc;
        __syncthreads();
        for (int d = 128; d > 0; d >>= 1) {
            if (threadIdx.x < d) s[threadIdx.x] |= s[threadIdx.x + d];
            __syncthreads();
        }
        if (threadIdx.x == 0) g_is64 = (s[0] == 0) ? 1 : 0;
    }
}

__global__ void k_hist(const unsigned* __restrict__ w, int n_edges) {
    int e = blockIdx.x * blockDim.x + threadIdx.x;
    if (e < n_edges) {
        int is64 = g_is64;
        atomicAdd(&g_deg_in [edge_col(w, e, is64)], 1);
        atomicAdd(&g_deg_out[edge_row(w, e, n_edges, is64)], 1);
    }
}

// ---------------- multi-block packed exclusive scan ----------------
__global__ __launch_bounds__(512)
void k_scan_part(int n_nodes) {
    __shared__ long long ws[16];
    const int tid = threadIdx.x, lane = tid & 31, wid = tid >> 5;
    int i0 = blockIdx.x * SCAN_CH + tid * 4;
    long long s = 0;
#pragma unroll
    for (int j = 0; j < 4; j++) {
        int i = i0 + j;
        if (i < n_nodes)
            s += ((long long)g_deg_out[i] << 32) | (unsigned)g_deg_in[i];
    }
#pragma unroll
    for (int d = 16; d > 0; d >>= 1) s += __shfl_down_sync(0xffffffff, s, d);
    if (lane == 0) ws[wid] = s;
    __syncthreads();
    if (wid == 0) {
        long long r = (lane < 16) ? ws[lane] : 0;
#pragma unroll
        for (int d = 8; d > 0; d >>= 1) r += __shfl_down_sync(0xffffffff, r, d);
        if (lane == 0) g_bsum[blockIdx.x] = r;
    }
}

__global__ void k_scan_bsum(int nb, int n_nodes) {
    int tid = threadIdx.x;                 // 64 threads
    long long v = (tid < nb) ? g_bsum[tid] : 0;
    long long t = v;
#pragma unroll
    for (int d = 1; d < 32; d <<= 1) {
        long long u = __shfl_up_sync(0xffffffff, t, d);
        if ((tid & 31) >= d) t += u;
    }
    __shared__ long long w0tot;
    if (tid == 31) w0tot = t;
    __syncthreads();
    if (tid >= 32) t += w0tot;
    if (tid < nb) g_bsum[tid] = t - v;     // exclusive
    if (tid == nb - 1) {                   // total -> sentinel offsets
        g_off_in [n_nodes] = (int)(t & 0xffffffffLL);
        g_off_out[n_nodes] = (int)((unsigned long long)t >> 32);
    }
}

__global__ __launch_bounds__(512)
void k_scan_final(int n_nodes) {
    __shared__ long long warpsum[16];
    const int tid = threadIdx.x, lane = tid & 31, wid = tid >> 5;
    const long long run = g_bsum[blockIdx.x];
    int i0 = blockIdx.x * SCAN_CH + tid * 4;
    long long v[4];
    long long s = 0;
#pragma unroll
    for (int j = 0; j < 4; j++) {
        int i = i0 + j;
        long long din = 0, dout = 0;
        if (i < n_nodes) {
            din  = g_deg_in[i];
            dout = g_deg_out[i];
            g_rin [i] = rsqrtf((float)(din  + 1));   // +1 self loop
            g_rout[i] = rsqrtf((float)(dout + 1));
        }
        v[j] = (dout << 32) | din;
        s += v[j];
    }
    long long t = s;
#pragma unroll
    for (int d = 1; d < 32; d <<= 1) {
        long long u = __shfl_up_sync(0xffffffff, t, d);
        if (lane >= d) t += u;
    }
    if (lane == 31) warpsum[wid] = t;
    __syncthreads();
    if (wid == 0) {
        long long w = (lane < 16) ? warpsum[lane] : 0;
#pragma unroll
        for (int d = 1; d < 16; d <<= 1) {
            long long u = __shfl_up_sync(0xffffffff, w, d);
            if (lane >= d) w += u;
        }
        if (lane < 16) warpsum[lane] = w;
    }
    __syncthreads();
    long long warpoff = (wid > 0) ? warpsum[wid - 1] : 0;
    long long excl = run + warpoff + (t - s);
#pragma unroll
    for (int j = 0; j < 4; j++) {
        int i = i0 + j;
        if (i < n_nodes) {
            g_off_in [i] = (int)(excl & 0xffffffffLL);
            g_off_out[i] = (int)((unsigned long long)excl >> 32);
        }
        excl += v[j];
    }
}

__global__ void k_fill(const unsigned* __restrict__ w, int n_edges) {
    int e = blockIdx.x * blockDim.x + threadIdx.x;
    if (e >= n_edges) return;
    int is64 = g_is64;
    int c = edge_col(w, e, is64);
    int r = edge_row(w, e, n_edges, is64);
    int p = atomicAdd(&g_fill_in[c], 1);
    g_src_f[g_off_in[c] + p] = r;
    int q = atomicAdd(&g_fill_out[r], 1);
    g_src_b[g_off_out[r] + q] = c;
}

// ---------------- W split prep: g_wb[n][512] = [Whi | Wlo] -------------------
__global__ void k_prep_w(const float* __restrict__ Wf, const float* __restrict__ Wb) {
    int idx = blockIdx.x * blockDim.x + threadIdx.x;
    if (idx >= 256 * 512) return;
    int n = idx >> 9;
    int k = idx & 511;
    int kk = k & 255;
    int sec = k >> 8;
    const float* Wsrc = (n < 128) ? (Wf + (size_t)n * D_IN) : (Wb + (size_t)(n - 128) * D_IN);
    float v = Wsrc[kk];
    __nv_bfloat16 hi = __float2bfloat16(v);
    g_wb[idx] = (sec == 0) ? hi : __float2bfloat16(v - __bfloat162float(hi));
}

// ---------------- mma.sync bf16 GEMM (R12 config): 128x64, 256 thr, 2 CTA/SM -----
// Grid: (4, m_tiles) — the 4 N-tiles sharing one M-tile are launch-adjacent.
// 8 warps as 4(M) x 2(N), warp tile 32x32. 8 K-chunks of 32; per chunk
// 3 sections: Ahi*Bhi + Alo*Bhi + Ahi*Blo.
#define SA_LD 40
__device__ __forceinline__ void mma16816(float* c, const uint32_t* a, const uint32_t* b) {
    asm volatile(
        "mma.sync.aligned.m16n8k16.row.col.f32.bf16.bf16.f32 "
        "{%0,%1,%2,%3}, {%4,%5,%6,%7}, {%8,%9}, {%0,%1,%2,%3};"
        : "+f"(c[0]), "+f"(c[1]), "+f"(c[2]), "+f"(c[3])
        : "r"(a[0]), "r"(a[1]), "r"(a[2]), "r"(a[3]), "r"(b[0]), "r"(b[1]));
}
__device__ __forceinline__ void ldsm4(uint32_t& r0, uint32_t& r1, uint32_t& r2, uint32_t& r3,
                                      uint32_t addr) {
    asm volatile("ldmatrix.sync.aligned.m8n8.x4.shared.b16 {%0,%1,%2,%3}, [%4];"
                 : "=r"(r0), "=r"(r1), "=r"(r2), "=r"(r3) : "r"(addr));
}
// convert 8 contiguous fp32 -> 8 bf16 hi + 8 bf16 lo, store as uint4 pair
__device__ __forceinline__ void cvt_store8(const float4& f0, const float4& f1,
                                           __nv_bfloat16* dh, __nv_bfloat16* dl) {
    float f[8] = {f0.x, f0.y, f0.z, f0.w, f1.x, f1.y, f1.z, f1.w};
    alignas(16) __nv_bfloat16 h[8];
    alignas(16) __nv_bfloat16 l[8];
#pragma unroll
    for (int j = 0; j < 8; j++) {
        h[j] = __float2bfloat16(f[j]);
        l[j] = __float2bfloat16(f[j] - __bfloat162float(h[j]));
    }
    *(uint4*)dh = *(uint4*)h;
    *(uint4*)dl = *(uint4*)l;
}

__global__ __launch_bounds__(256, 2)
void k_gemm_mma(const float* __restrict__ x, int n_nodes) {
    __shared__ __nv_bfloat16 sAh[2][128 * SA_LD];
    __shared__ __nv_bfloat16 sAl[2][128 * SA_LD];
    __shared__ __nv_bfloat16 sBh[2][64 * SA_LD];
    __shared__ __nv_bfloat16 sBl[2][64 * SA_LD];

    const int tid  = threadIdx.x;
    const int wid  = tid >> 5;
    const int lane = tid & 31;
    const int qr   = lane >> 2;          // 0..7
    const int qc   = lane & 3;           // 0..3
    const int wm   = (wid & 3) * 32;     // warp M offset in block
    const int wn   = (wid >> 2) * 32;    // warp N offset in block
    const int m0   = blockIdx.y * 128;   // M tile (slow axis)
    const int n0   = blockIdx.x * 64;    // N tile (fast axis: 4 adjacent share A)
    const int half = blockIdx.x >> 1;    // 0: fwd (rout scale), 1: bwd (rin scale)

    const int lrow = lane & 15;          // ldmatrix row
    const int lksl = lane >> 4;          // ldmatrix 16B half-select

    // loaders: each thread covers rows arow0 & arow1, 8 cols at apart*8
    const int arow0 = tid >> 2;          // 0..63
    const int arow1 = arow0 + 64;        // 64..127
    const int apart = tid & 3;
    int anode0 = m0 + arow0; if (anode0 >= n_nodes) anode0 = n_nodes - 1;
    int anode1 = m0 + arow1; if (anode1 >= n_nodes) anode1 = n_nodes - 1;
    const float* ap0 = x + (size_t)anode0 * D_IN + apart * 8;
    const float* ap1 = x + (size_t)anode1 * D_IN + apart * 8;
    const __nv_bfloat16* bp = g_wb + (size_t)(n0 + arow0) * 512 + apart * 8;

    float acc[2][4][4];
#pragma unroll
    for (int mt = 0; mt < 2; mt++)
#pragma unroll
        for (int nt = 0; nt < 4; nt++)
#pragma unroll
            for (int q = 0; q < 4; q++) acc[mt][nt][q] = 0.f;

    float4 fa0, fa1, fa2, fa3;
    uint4 rbh, rbl;

    // preload chunk 0
    fa0 = *(const float4*)(ap0);     fa1 = *(const float4*)(ap0 + 4);
    fa2 = *(const float4*)(ap1);     fa3 = *(const float4*)(ap1 + 4);
    rbh = *(const uint4*)(bp);
    rbl = *(const uint4*)(bp + 256);
    cvt_store8(fa0, fa1, sAh[0] + arow0 * SA_LD + apart * 8, sAl[0] + arow0 * SA_LD + apart * 8);
    cvt_store8(fa2, fa3, sAh[0] + arow1 * SA_LD + apart * 8, sAl[0] + arow1 * SA_LD + apart * 8);
    *(uint4*)(sBh[0] + arow0 * SA_LD + apart * 8) = rbh;
    *(uint4*)(sBl[0] + arow0 * SA_LD + apart * 8) = rbl;
    __syncthreads();

    for (int kc = 0; kc < 8; kc++) {
        const int cur = kc & 1;
        const int nxt = cur ^ 1;

        if (kc < 7) {
            const int ko = (kc + 1) * 32;
            fa0 = *(const float4*)(ap0 + ko);     fa1 = *(const float4*)(ap0 + ko + 4);
            fa2 = *(const float4*)(ap1 + ko);     fa3 = *(const float4*)(ap1 + ko + 4);
            rbh = *(const uint4*)(bp + ko);
            rbl = *(const uint4*)(bp + 256 + ko);
        }

        const uint32_t sah = (uint32_t)__cvta_generic_to_shared(sAh[cur]);
        const uint32_t sal = (uint32_t)__cvta_generic_to_shared(sAl[cur]);
        const uint32_t sbh = (uint32_t)__cvta_generic_to_shared(sBh[cur]);
        const uint32_t sbl = (uint32_t)__cvta_generic_to_shared(sBl[cur]);

#pragma unroll
        for (int ks = 0; ks < 2; ks++) {
            const int kb = ks * 16;
            uint32_t ah[2][4], al[2][4], bh[2][4], bl[2][4];
#pragma unroll
            for (int mt = 0; mt < 2; mt++) {
                uint32_t off = ((wm + mt * 16 + lrow) * SA_LD + kb + lksl * 8) * 2;
                ldsm4(ah[mt][0], ah[mt][1], ah[mt][2], ah[mt][3], sah + off);
                ldsm4(al[mt][0], al[mt][1], al[mt][2], al[mt][3], sal + off);
            }
#pragma unroll
            for (int np = 0; np < 2; np++) {
                uint32_t off = ((wn + np * 16 + lrow) * SA_LD + kb + lksl * 8) * 2;
                ldsm4(bh[np][0], bh[np][1], bh[np][2], bh[np][3], sbh + off);
                ldsm4(bl[np][0], bl[np][1], bl[np][2], bl[np][3], sbl + off);
            }
#pragma unroll
            for (int mt = 0; mt < 2; mt++)
#pragma unroll
                for (int np = 0; np < 2; np++) {
                    uint32_t b0h[2] = { bh[np][0], bh[np][2] };
                    uint32_t b1h[2] = { bh[np][1], bh[np][3] };
                    uint32_t b0l[2] = { bl[np][0], bl[np][2] };
                    uint32_t b1l[2] = { bl[np][1], bl[np][3] };
                    mma16816(acc[mt][np * 2 + 0], ah[mt], b0h);
                    mma16816(acc[mt][np * 2 + 1], ah[mt], b1h);
                    mma16816(acc[mt][np * 2 + 0], al[mt], b0h);
                    mma16816(acc[mt][np * 2 + 1], al[mt], b1h);
                    mma16816(acc[mt][np * 2 + 0], ah[mt], b0l);
                    mma16816(acc[mt][np * 2 + 1], ah[mt], b1l);
                }
        }

        if (kc < 7) {
            cvt_store8(fa0, fa1, sAh[nxt] + arow0 * SA_LD + apart * 8, sAl[nxt] + arow0 * SA_LD + apart * 8);
            cvt_store8(fa2, fa3, sAh[nxt] + arow1 * SA_LD + apart * 8, sAl[nxt] + arow1 * SA_LD + apart * 8);
            *(uint4*)(sBh[nxt] + arow0 * SA_LD + apart * 8) = rbh;
            *(uint4*)(sBl[nxt] + arow0 * SA_LD + apart * 8) = rbl;
            __syncthreads();
        }
    }

    // epilogue: pre-scale by rout (fwd half) / rin (bwd half), write fp16 g_feat
#pragma unroll
    for (int mt = 0; mt < 2; mt++) {
        int r0 = m0 + wm + mt * 16 + qr;
        int r1 = r0 + 8;
        float s0 = 0.f, s1 = 0.f;
        if (r0 < n_nodes) s0 = half ? g_rin[r0] : g_rout[r0];
        if (r1 < n_nodes) s1 = half ? g_rin[r1] : g_rout[r1];
#pragma unroll
        for (int nt = 0; nt < 4; nt++) {
            int cix = n0 + wn + nt * 8 + 2 * qc;
            if (r0 < n_nodes) {
                __half2 v = __floats2half2_rn(s0 * acc[mt][nt][0], s0 * acc[mt][nt][1]);
                *(__half2*)(g_feat + (size_t)r0 * D_OUT + cix) = v;
            }
            if (r1 < n_nodes) {
                __half2 v = __floats2half2_rn(s1 * acc[mt][nt][2], s1 * acc[mt][nt][3]);
                *(__half2*)(g_feat + (size_t)r1 * D_OUT + cix) = v;
            }
        }
    }
}

// ---------------- gather: 1 warp per (node,half); 8B lane loads -------------------
__global__ __launch_bounds__(128)
void k_gather(const float* __restrict__ bias, float* __restrict__ y, int n_nodes) {
    const int w    = threadIdx.x >> 5;       // 0..3
    const int lane = threadIdx.x & 31;
    const int node = blockIdx.x * 2 + (w >> 1);
    const int h    = w & 1;                  // 0: fwd, 1: bwd
    if (node >= n_nodes) return;

    int s, e;
    const int* __restrict__ srcs;
    float rs;
    if (h == 0) {
        s = g_off_in[node]; e = g_off_in[node + 1];
        srcs = g_src_f;
        rs = g_rin[node];
    } else {
        s = g_off_out[node]; e = g_off_out[node + 1];
        srcs = g_src_b;
        rs = g_rout[node];
    }

    const int hp = h * 32 + lane;            // uint2 index in 64-uint2 row
    const uint2* __restrict__ fp = (const uint2*)g_feat;

    float4 acc;
    {
        uint2 v = fp[(size_t)node * 64 + hp];   // self loop (pre-scaled)
        float2 a = __half22float2(*(__half2*)&v.x);
        float2 b = __half22float2(*(__half2*)&v.y);
        acc = make_float4(a.x, a.y, b.x, b.y);
    }
#pragma unroll 4
    for (int k = s; k < e; k++) {
        int src = __ldg(&srcs[k]);
        uint2 v = __ldg(&fp[(size_t)src * 64 + hp]);
        float2 a = __half22float2(*(__half2*)&v.x);
        float2 b = __half22float2(*(__half2*)&v.y);
        acc.x += a.x; acc.y += a.y; acc.z += b.x; acc.w += b.y;
    }

    const int coff = hp * 4;
    float4 b4 = *(const float4*)(bias + coff);
    float4 o = make_float4(b4.x + rs * acc.x, b4.y + rs * acc.y,
                           b4.z + rs * acc.z, b4.w + rs * acc.w);
    *(float4*)(y + (size_t)node * D_OUT + coff) = o;
}

// ---------------- launch ----------------
extern "C" void kernel_launch(void* const* d_in, const int* in_sizes, int n_in,
                              void* d_out, int out_size) {
    const float*    x    = (const float*)d_in[0];
    const unsigned* ew   = (const unsigned*)d_in[1];
    const float*    Wf   = (const float*)d_in[2];
    const float*    Wb   = (const float*)d_in[3];
    const float*    bias = (const float*)d_in[4];
    float* y = (float*)d_out;

    const int n_nodes = in_sizes[0] / D_IN;
    const int n_edges = in_sizes[1] / 2;

    int check = 8192;
    if (check > 2 * n_edges) check = 2 * n_edges;

    k_detect_zero<<<(n_nodes + 255) / 256, 256>>>(ew, check, n_nodes);
    k_hist<<<(n_edges + 255) / 256, 256>>>(ew, n_edges);

    const int nb = (n_nodes + SCAN_CH - 1) / SCAN_CH;
    k_scan_part <<<nb, 512>>>(n_nodes);
    k_scan_bsum <<<1, 64>>>(nb, n_nodes);
    k_scan_final<<<nb, 512>>>(n_nodes);

    k_fill<<<(n_edges + 255) / 256, 256>>>(ew, n_edges);

    k_prep_w<<<(256 * 512 + 255) / 256, 256>>>(Wf, Wb);

    dim3 ggrid(4, (n_nodes + 127) / 128);
    k_gemm_mma<<<ggrid, 256>>>(x, n_nodes);

    dim3 grid_g((n_nodes + 1) / 2, 1);
    k_gather<<<grid_g, 128>>>(bias, y, n_nodes);
}

// round 15
// speedup vs baseline: 1.0269x; 1.0089x over previous
#include <cuda_runtime.h>
#include <cuda_bf16.h>
#include <cuda_fp16.h>
#include <cstdint>

// Problem shape constants (fixed by setup_inputs)
#define MAX_NODES 100000
#define MAX_EDGES 1600000
#define D_IN   256
#define D_HALF 128
#define D_OUT  256   // concat(forward, backward)

#define SCAN_CH 2048        // elems per scan block (512 thr * 4)
#define MAX_SCAN_BLOCKS 64

// ---------------- device scratch (no allocations allowed) ----------------
__device__ int   g_is64;
__device__ int   g_deg_in [MAX_NODES];
__device__ int   g_deg_out[MAX_NODES];
__device__ int   g_off_in [MAX_NODES + 1];
__device__ int   g_off_out[MAX_NODES + 1];
__device__ int   g_fill_in [MAX_NODES];
__device__ int   g_fill_out[MAX_NODES];
__device__ int   g_src_f[MAX_EDGES];
__device__ int   g_src_b[MAX_EDGES];
__device__ float g_rin [MAX_NODES];
__device__ float g_rout[MAX_NODES];
__device__ long long g_bsum[MAX_SCAN_BLOCKS];
__device__ __half g_feat[(size_t)MAX_NODES * D_OUT];      // PRE-SCALED fp16: fwd*rout[n], bwd*rin[n]
__device__ __nv_bfloat16 g_wb [(size_t)256 * 512];        // B [n][512]: 0-255 Whi, 256-511 Wlo

// ---------------- edge accessors (dtype detected at runtime) ----------------
__device__ __forceinline__ int edge_col(const unsigned* __restrict__ w, int e, int is64) {
    return (int)(is64 ? w[2u * (unsigned)e] : w[(unsigned)e]);
}
__device__ __forceinline__ int edge_row(const unsigned* __restrict__ w, int e, int n_edges, int is64) {
    return (int)(is64 ? w[2u * (unsigned)(n_edges + e)] : w[(unsigned)(n_edges + e)]);
}

// ---------------- detect dtype + zero counters (merged) ----------------
__global__ void k_detect_zero(const unsigned* __restrict__ w, int n_words_check, int n_nodes) {
    int i = blockIdx.x * blockDim.x + threadIdx.x;
    if (i < n_nodes) {
        g_deg_in[i]   = 0;
        g_deg_out[i]  = 0;
        g_fill_in[i]  = 0;
        g_fill_out[i] = 0;
    }
    if (blockIdx.x == 0) {
        __shared__ unsigned s[256];
        unsigned acc = 0;
        for (int k = threadIdx.x; k < n_words_check; k += 256)
            if (k & 1) acc |= w[k];
        s[threadIdx.x] = acc;
        __syncthreads();
        for (int d = 128; d > 0; d >>= 1) {
            if (threadIdx.x < d) s[threadIdx.x] |= s[threadIdx.x + d];
            __syncthreads();
        }
        if (threadIdx.x == 0) g_is64 = (s[0] == 0) ? 1 : 0;
    }
}

// ---------------- hist + W-prep fused (independent work, appended blocks) ---------
__global__ void k_hist_prepw(const unsigned* __restrict__ w, int n_edges, int hist_blocks,
                             const float* __restrict__ Wf, const float* __restrict__ Wb) {
    if (blockIdx.x < (unsigned)hist_blocks) {
        int e = blockIdx.x * blockDim.x + threadIdx.x;
        if (e < n_edges) {
            int is64 = g_is64;
            atomicAdd(&g_deg_in [edge_col(w, e, is64)], 1);
            atomicAdd(&g_deg_out[edge_row(w, e, n_edges, is64)], 1);
        }
    } else {
        int idx = (blockIdx.x - hist_blocks) * blockDim.x + threadIdx.x;
        if (idx < 256 * 512) {
            int n = idx >> 9;
            int k = idx & 511;
            int kk = k & 255;
            int sec = k >> 8;
            const float* Wsrc = (n < 128) ? (Wf + (size_t)n * D_IN)
                                          : (Wb + (size_t)(n - 128) * D_IN);
            float v = Wsrc[kk];
            __nv_bfloat16 hi = __float2bfloat16(v);
            g_wb[idx] = (sec == 0) ? hi : __float2bfloat16(v - __bfloat162float(hi));
        }
    }
}

// ---------------- multi-block packed exclusive scan ----------------
__global__ __launch_bounds__(512)
void k_scan_part(int n_nodes) {
    __shared__ long long ws[16];
    const int tid = threadIdx.x, lane = tid & 31, wid = tid >> 5;
    int i0 = blockIdx.x * SCAN_CH + tid * 4;
    long long s = 0;
#pragma unroll
    for (int j = 0; j < 4; j++) {
        int i = i0 + j;
        if (i < n_nodes)
            s += ((long long)g_deg_out[i] << 32) | (unsigned)g_deg_in[i];
    }
#pragma unroll
    for (int d = 16; d > 0; d >>= 1) s += __shfl_down_sync(0xffffffff, s, d);
    if (lane == 0) ws[wid] = s;
    __syncthreads();
    if (wid == 0) {
        long long r = (lane < 16) ? ws[lane] : 0;
#pragma unroll
        for (int d = 8; d > 0; d >>= 1) r += __shfl_down_sync(0xffffffff, r, d);
        if (lane == 0) g_bsum[blockIdx.x] = r;
    }
}

__global__ void k_scan_bsum(int nb, int n_nodes) {
    int tid = threadIdx.x;                 // 64 threads
    long long v = (tid < nb) ? g_bsum[tid] : 0;
    long long t = v;
#pragma unroll
    for (int d = 1; d < 32; d <<= 1) {
        long long u = __shfl_up_sync(0xffffffff, t, d);
        if ((tid & 31) >= d) t += u;
    }
    __shared__ long long w0tot;
    if (tid == 31) w0tot = t;
    __syncthreads();
    if (tid >= 32) t += w0tot;
    if (tid < nb) g_bsum[tid] = t - v;     // exclusive
    if (tid == nb - 1) {                   // total -> sentinel offsets
        g_off_in [n_nodes] = (int)(t & 0xffffffffLL);
        g_off_out[n_nodes] = (int)((unsigned long long)t >> 32);
    }
}

__global__ __launch_bounds__(512)
void k_scan_final(int n_nodes) {
    __shared__ long long warpsum[16];
    const int tid = threadIdx.x, lane = tid & 31, wid = tid >> 5;
    const long long run = g_bsum[blockIdx.x];
    int i0 = blockIdx.x * SCAN_CH + tid * 4;
    long long v[4];
    long long s = 0;
#pragma unroll
    for (int j = 0; j < 4; j++) {
        int i = i0 + j;
        long long din = 0, dout = 0;
        if (i < n_nodes) {
            din  = g_deg_in[i];
            dout = g_deg_out[i];
            g_rin [i] = rsqrtf((float)(din  + 1));   // +1 self loop
            g_rout[i] = rsqrtf((float)(dout + 1));
        }
        v[j] = (dout << 32) | din;
        s += v[j];
    }
    long long t = s;
#pragma unroll
    for (int d = 1; d < 32; d <<= 1) {
        long long u = __shfl_up_sync(0xffffffff, t, d);
        if (lane >= d) t += u;
    }
    if (lane == 31) warpsum[wid] = t;
    __syncthreads();
    if (wid == 0) {
        long long w = (lane < 16) ? warpsum[lane] : 0;
#pragma unroll
        for (int d = 1; d < 16; d <<= 1) {
            long long u = __shfl_up_sync(0xffffffff, w, d);
            if (lane >= d) w += u;
        }
        if (lane < 16) warpsum[lane] = w;
    }
    __syncthreads();
    long long warpoff = (wid > 0) ? warpsum[wid - 1] : 0;
    long long excl = run + warpoff + (t - s);
#pragma unroll
    for (int j = 0; j < 4; j++) {
        int i = i0 + j;
        if (i < n_nodes) {
            g_off_in [i] = (int)(excl & 0xffffffffLL);
            g_off_out[i] = (int)((unsigned long long)excl >> 32);
        }
        excl += v[j];
    }
}

// ---------------- mma.sync bf16 GEMM + fused CSR fill (appended blocks) -----------
// GEMM grid part: (4, m_tiles) — 4 N-tiles share one M-tile's A rows (L2 reuse).
// Fill part: blockIdx.y >= m_tiles; each fill block handles 1024 edges.
// GEMM: 128x64 tile, 256 thr, 2 CTA/SM; 8 warps 4(M)x2(N); warp tile 32x32.
// 8 K-chunks of 32; per chunk 3 sections: Ahi*Bhi + Alo*Bhi + Ahi*Blo.
#define SA_LD 40
__device__ __forceinline__ void mma16816(float* c, const uint32_t* a, const uint32_t* b) {
    asm volatile(
        "mma.sync.aligned.m16n8k16.row.col.f32.bf16.bf16.f32 "
        "{%0,%1,%2,%3}, {%4,%5,%6,%7}, {%8,%9}, {%0,%1,%2,%3};"
        : "+f"(c[0]), "+f"(c[1]), "+f"(c[2]), "+f"(c[3])
        : "r"(a[0]), "r"(a[1]), "r"(a[2]), "r"(a[3]), "r"(b[0]), "r"(b[1]));
}
__device__ __forceinline__ void ldsm4(uint32_t& r0, uint32_t& r1, uint32_t& r2, uint32_t& r3,
                                      uint32_t addr) {
    asm volatile("ldmatrix.sync.aligned.m8n8.x4.shared.b16 {%0,%1,%2,%3}, [%4];"
                 : "=r"(r0), "=r"(r1), "=r"(r2), "=r"(r3) : "r"(addr));
}
// convert 8 contiguous fp32 -> 8 bf16 hi + 8 bf16 lo, store as uint4 pair
__device__ __forceinline__ void cvt_store8(const float4& f0, const float4& f1,
                                           __nv_bfloat16* dh, __nv_bfloat16* dl) {
    float f[8] = {f0.x, f0.y, f0.z, f0.w, f1.x, f1.y, f1.z, f1.w};
    alignas(16) __nv_bfloat16 h[8];
    alignas(16) __nv_bfloat16 l[8];
#pragma unroll
    for (int j = 0; j < 8; j++) {
        h[j] = __float2bfloat16(f[j]);
        l[j] = __float2bfloat16(f[j] - __bfloat162float(h[j]));
    }
    *(uint4*)dh = *(uint4*)h;
    *(uint4*)dl = *(uint4*)l;
}

__global__ __launch_bounds__(256, 2)
void k_gemm_fill(const float* __restrict__ x, const unsigned* __restrict__ ew,
                 int n_nodes, int n_edges, int m_tiles) {
    __shared__ __nv_bfloat16 sAh[2][128 * SA_LD];
    __shared__ __nv_bfloat16 sAl[2][128 * SA_LD];
    __shared__ __nv_bfloat16 sBh[2][64 * SA_LD];
    __shared__ __nv_bfloat16 sBl[2][64 * SA_LD];

    const int tid  = threadIdx.x;

    // ---------- fill path (appended blocks) ----------
    if ((int)blockIdx.y >= m_tiles) {
        const int fb   = ((int)blockIdx.y - m_tiles) * 4 + (int)blockIdx.x;
        const int base = fb * 1024;
        const int is64 = g_is64;
#pragma unroll
        for (int i = 0; i < 4; i++) {
            int e = base + i * 256 + tid;
            if (e < n_edges) {
                int c = edge_col(ew, e, is64);
                int r = edge_row(ew, e, n_edges, is64);
                int p = atomicAdd(&g_fill_in[c], 1);
                g_src_f[g_off_in[c] + p] = r;
                int q = atomicAdd(&g_fill_out[r], 1);
                g_src_b[g_off_out[r] + q] = c;
            }
        }
        return;
    }

    // ---------- GEMM path ----------
    const int wid  = tid >> 5;
    const int lane = tid & 31;
    const int qr   = lane >> 2;          // 0..7
    const int qc   = lane & 3;           // 0..3
    const int wm   = (wid & 3) * 32;     // warp M offset in block
    const int wn   = (wid >> 2) * 32;    // warp N offset in block
    const int m0   = blockIdx.y * 128;   // M tile (slow axis)
    const int n0   = blockIdx.x * 64;    // N tile (fast axis: 4 adjacent share A)
    const int half = blockIdx.x >> 1;    // 0: fwd (rout scale), 1: bwd (rin scale)

    const int lrow = lane & 15;          // ldmatrix row
    const int lksl = lane >> 4;          // ldmatrix 16B half-select

    // loaders: each thread covers rows arow0 & arow1, 8 cols at apart*8
    const int arow0 = tid >> 2;          // 0..63
    const int arow1 = arow0 + 64;        // 64..127
    const int apart = tid & 3;
    int anode0 = m0 + arow0; if (anode0 >= n_nodes) anode0 = n_nodes - 1;
    int anode1 = m0 + arow1; if (anode1 >= n_nodes) anode1 = n_nodes - 1;
    const float* ap0 = x + (size_t)anode0 * D_IN + apart * 8;
    const float* ap1 = x + (size_t)anode1 * D_IN + apart * 8;
    const __nv_bfloat16* bp = g_wb + (size_t)(n0 + arow0) * 512 + apart * 8;

    float acc[2][4][4];
#pragma unroll
    for (int mt = 0; mt < 2; mt++)
#pragma unroll
        for (int nt = 0; nt < 4; nt++)
#pragma unroll
            for (int q = 0; q < 4; q++) acc[mt][nt][q] = 0.f;

    float4 fa0, fa1, fa2, fa3;
    uint4 rbh, rbl;

    // preload chunk 0
    fa0 = *(const float4*)(ap0);     fa1 = *(const float4*)(ap0 + 4);
    fa2 = *(const float4*)(ap1);     fa3 = *(const float4*)(ap1 + 4);
    rbh = *(const uint4*)(bp);
    rbl = *(const uint4*)(bp + 256);
    cvt_store8(fa0, fa1, sAh[0] + arow0 * SA_LD + apart * 8, sAl[0] + arow0 * SA_LD + apart * 8);
    cvt_store8(fa2, fa3, sAh[0] + arow1 * SA_LD + apart * 8, sAl[0] + arow1 * SA_LD + apart * 8);
    *(uint4*)(sBh[0] + arow0 * SA_LD + apart * 8) = rbh;
    *(uint4*)(sBl[0] + arow0 * SA_LD + apart * 8) = rbl;
    __syncthreads();

    for (int kc = 0; kc < 8; kc++) {
        const int cur = kc & 1;
        const int nxt = cur ^ 1;

        if (kc < 7) {
            const int ko = (kc + 1) * 32;
            fa0 = *(const float4*)(ap0 + ko);     fa1 = *(const float4*)(ap0 + ko + 4);
            fa2 = *(const float4*)(ap1 + ko);     fa3 = *(const float4*)(ap1 + ko + 4);
            rbh = *(const uint4*)(bp + ko);
            rbl = *(const uint4*)(bp + 256 + ko);
        }

        const uint32_t sah = (uint32_t)__cvta_generic_to_shared(sAh[cur]);
        const uint32_t sal = (uint32_t)__cvta_generic_to_shared(sAl[cur]);
        const uint32_t sbh = (uint32_t)__cvta_generic_to_shared(sBh[cur]);
        const uint32_t sbl = (uint32_t)__cvta_generic_to_shared(sBl[cur]);

#pragma unroll
        for (int ks = 0; ks < 2; ks++) {
            const int kb = ks * 16;
            uint32_t ah[2][4], al[2][4], bh[2][4], bl[2][4];
#pragma unroll
            for (int mt = 0; mt < 2; mt++) {
                uint32_t off = ((wm + mt * 16 + lrow) * SA_LD + kb + lksl * 8) * 2;
                ldsm4(ah[mt][0], ah[mt][1], ah[mt][2], ah[mt][3], sah + off);
                ldsm4(al[mt][0], al[mt][1], al[mt][2], al[mt][3], sal + off);
            }
#pragma unroll
            for (int np = 0; np < 2; np++) {
                uint32_t off = ((wn + np * 16 + lrow) * SA_LD + kb + lksl * 8) * 2;
                ldsm4(bh[np][0], bh[np][1], bh[np][2], bh[np][3], sbh + off);
                ldsm4(bl[np][0], bl[np][1], bl[np][2], bl[np][3], sbl + off);
            }
#pragma unroll
            for (int mt = 0; mt < 2; mt++)
#pragma unroll
                for (int np = 0; np < 2; np++) {
                    uint32_t b0h[2] = { bh[np][0], bh[np][2] };
                    uint32_t b1h[2] = { bh[np][1], bh[np][3] };
                    uint32_t b0l[2] = { bl[np][0], bl[np][2] };
                    uint32_t b1l[2] = { bl[np][1], bl[np][3] };
                    mma16816(acc[mt][np * 2 + 0], ah[mt], b0h);
                    mma16816(acc[mt][np * 2 + 1], ah[mt], b1h);
                    mma16816(acc[mt][np * 2 + 0], al[mt], b0h);
                    mma16816(acc[mt][np * 2 + 1], al[mt], b1h);
                    mma16816(acc[mt][np * 2 + 0], ah[mt], b0l);
                    mma16816(acc[mt][np * 2 + 1], ah[mt], b1l);
                }
        }

        if (kc < 7) {
            cvt_store8(fa0, fa1, sAh[nxt] + arow0 * SA_LD + apart * 8, sAl[nxt] + arow0 * SA_LD + apart * 8);
            cvt_store8(fa2, fa3, sAh[nxt] + arow1 * SA_LD + apart * 8, sAl[nxt] + arow1 * SA_LD + apart * 8);
            *(uint4*)(sBh[nxt] + arow0 * SA_LD + apart * 8) = rbh;
            *(uint4*)(sBl[nxt] + arow0 * SA_LD + apart * 8) = rbl;
            __syncthreads();
        }
    }

    // epilogue: pre-scale by rout (fwd half) / rin (bwd half), write fp16 g_feat
#pragma unroll
    for (int mt = 0; mt < 2; mt++) {
        int r0 = m0 + wm + mt * 16 + qr;
        int r1 = r0 + 8;
        float s0 = 0.f, s1 = 0.f;
        if (r0 < n_nodes) s0 = half ? g_rin[r0] : g_rout[r0];
        if (r1 < n_nodes) s1 = half ? g_rin[r1] : g_rout[r1];
#pragma unroll
        for (int nt = 0; nt < 4; nt++) {
            int cix = n0 + wn + nt * 8 + 2 * qc;
            if (r0 < n_nodes) {
                __half2 v = __floats2half2_rn(s0 * acc[mt][nt][0], s0 * acc[mt][nt][1]);
                *(__half2*)(g_feat + (size_t)r0 * D_OUT + cix) = v;
            }
            if (r1 < n_nodes) {
                __half2 v = __floats2half2_rn(s1 * acc[mt][nt][2], s1 * acc[mt][nt][3]);
                *(__half2*)(g_feat + (size_t)r1 * D_OUT + cix) = v;
            }
        }
    }
}

// ---------------- gather: 1 warp per (node,half); 8B lane loads -------------------
__global__ __launch_bounds__(128)
void k_gather(const float* __restrict__ bias, float* __restrict__ y, int n_nodes) {
    const int w    = threadIdx.x >> 5;       // 0..3
    const int lane = threadIdx.x & 31;
    const int node = blockIdx.x * 2 + (w >> 1);
    const int h    = w & 1;                  // 0: fwd, 1: bwd
    if (node >= n_nodes) return;

    int s, e;
    const int* __restrict__ srcs;
    float rs;
    if (h == 0) {
        s = g_off_in[node]; e = g_off_in[node + 1];
        srcs = g_src_f;
        rs = g_rin[node];
    } else {
        s = g_off_out[node]; e = g_off_out[node + 1];
        srcs = g_src_b;
        rs = g_rout[node];
    }

    const int hp = h * 32 + lane;            // uint2 index in 64-uint2 row
    const uint2* __restrict__ fp = (const uint2*)g_feat;

    float4 acc;
    {
        uint2 v = fp[(size_t)node * 64 + hp];   // self loop (pre-scaled)
        float2 a = __half22float2(*(__half2*)&v.x);
        float2 b = __half22float2(*(__half2*)&v.y);
        acc = make_float4(a.x, a.y, b.x, b.y);
    }
#pragma unroll 4
    for (int k = s; k < e; k++) {
        int src = __ldg(&srcs[k]);
        uint2 v = __ldg(&fp[(size_t)src * 64 + hp]);
        float2 a = __half22float2(*(__half2*)&v.x);
        float2 b = __half22float2(*(__half2*)&v.y);
        acc.x += a.x; acc.y += a.y; acc.z += b.x; acc.w += b.y;
    }

    const int coff = hp * 4;
    float4 b4 = *(const float4*)(bias + coff);
    float4 o = make_float4(b4.x + rs * acc.x, b4.y + rs * acc.y,
                           b4.z + rs * acc.z, b4.w + rs * acc.w);
    *(float4*)(y + (size_t)node * D_OUT + coff) = o;
}

// ---------------- launch ----------------
extern "C" void kernel_launch(void* const* d_in, const int* in_sizes, int n_in,
                              void* d_out, int out_size) {
    const float*    x    = (const float*)d_in[0];
    const unsigned* ew   = (const unsigned*)d_in[1];
    const float*    Wf   = (const float*)d_in[2];
    const float*    Wb   = (const float*)d_in[3];
    const float*    bias = (const float*)d_in[4];
    float* y = (float*)d_out;

    const int n_nodes = in_sizes[0] / D_IN;
    const int n_edges = in_sizes[1] / 2;

    int check = 8192;
    if (check > 2 * n_edges) check = 2 * n_edges;

    k_detect_zero<<<(n_nodes + 255) / 256, 256>>>(ew, check, n_nodes);

    const int hist_blocks = (n_edges + 255) / 256;
    const int prep_blocks = (256 * 512 + 255) / 256;
    k_hist_prepw<<<hist_blocks + prep_blocks, 256>>>(ew, n_edges, hist_blocks, Wf, Wb);

    const int nb = (n_nodes + SCAN_CH - 1) / SCAN_CH;
    k_scan_part <<<nb, 512>>>(n_nodes);
    k_scan_bsum <<<1, 64>>>(nb, n_nodes);
    k_scan_final<<<nb, 512>>>(n_nodes);

    const int m_tiles     = (n_nodes + 127) / 128;
    const int fill_blocks = (n_edges + 1023) / 1024;
    const int fill_y      = (fill_blocks + 3) / 4;
    dim3 ggrid(4, m_tiles + fill_y);
    k_gemm_fill<<<ggrid, 256>>>(x, ew, n_nodes, n_edges, m_tiles);

    dim3 grid_g((n_nodes + 1) / 2, 1);
    k_gather<<<grid_g, 128>>>(bias, y, n_nodes);
}